// round 1
// baseline (speedup 1.0000x reference)
#include <cuda_runtime.h>
#include <cstdint>

// ---------------------------------------------------------------------------
// GCN: 4 layers, N=100000 nodes, E=1600000 edges, 128->128->128->128->64
// Strategy:
//   1. Per-launch preprocessing: deg (with self-loop +1), dinv=rsqrt(deg),
//      CSR-by-destination build (count -> scan -> place).
//   2. Per layer: dense GEMM h = x@W  (fp32 tiled SGEMM, 128x64 tiles)
//                 then warp-per-node aggregation: out[i] = b + sum_j norm_j*h[src_j]
//                 + dinv[i]^2 * h[i] (self loop), fused bias + relu.
// No atomic floats in the hot path; feature matrices (51MB) are L2-resident.
// ---------------------------------------------------------------------------

#define N_NODES 100000
#define N_EDGES 1600000
#define DIM 128

// ----------------------------- scratch (device globals; no allocs allowed) --
__device__ float g_deg[N_NODES];        // degree, then overwritten semantics kept separate
__device__ float g_dinv[N_NODES];
__device__ float g_self[N_NODES];       // dinv^2 (self-loop norm)
__device__ int   g_counts[N_NODES];
__device__ int   g_offsets[N_NODES + 1];
__device__ int   g_cursor[N_NODES];
__device__ int   g_blocksums[256];
__device__ int   g_src_sorted[N_EDGES];
__device__ float g_norm_sorted[N_EDGES];
__device__ float g_bufA[(size_t)N_NODES * DIM];
__device__ float g_bufB[(size_t)N_NODES * DIM];

// ----------------------------- preprocessing kernels ------------------------
__global__ void k_init_nodes() {
    int i = blockIdx.x * blockDim.x + threadIdx.x;
    if (i < N_NODES) {
        g_deg[i]    = 1.0f;   // self-loop weight
        g_counts[i] = 0;
        g_cursor[i] = 0;
    }
}

__global__ void k_edge_degree(const int* __restrict__ ei, const float* __restrict__ w) {
    int e = blockIdx.x * blockDim.x + threadIdx.x;
    if (e < N_EDGES) {
        int dst = ei[N_EDGES + e];
        atomicAdd(&g_deg[dst], w[e]);
        atomicAdd(&g_counts[dst], 1);
    }
}

__global__ void k_dinv() {
    int i = blockIdx.x * blockDim.x + threadIdx.x;
    if (i < N_NODES) {
        float d = g_deg[i];
        float r = (d > 0.0f) ? rsqrtf(d) : 0.0f;
        g_dinv[i] = r;
        g_self[i] = r * r;
    }
}

// ---- exclusive scan of g_counts into g_offsets (3 passes) ----
#define SCAN_BS 1024
__global__ void k_scanA() {
    __shared__ int s[SCAN_BS];
    int t = threadIdx.x;
    int i = blockIdx.x * SCAN_BS + t;
    int v = (i < N_NODES) ? g_counts[i] : 0;
    s[t] = v;
    __syncthreads();
    for (int off = 1; off < SCAN_BS; off <<= 1) {
        int x = (t >= off) ? s[t - off] : 0;
        __syncthreads();
        s[t] += x;
        __syncthreads();
    }
    if (i < N_NODES) g_offsets[i + 1] = s[t];          // inclusive within block
    if (t == SCAN_BS - 1) g_blocksums[blockIdx.x] = s[t];
}

__global__ void k_scanB(int nblocks) {
    if (threadIdx.x == 0 && blockIdx.x == 0) {
        int run = 0;
        for (int b = 0; b < nblocks; b++) {
            int v = g_blocksums[b];
            g_blocksums[b] = run;                      // exclusive
            run += v;
        }
    }
}

__global__ void k_scanC() {
    int t = threadIdx.x;
    int i = blockIdx.x * SCAN_BS + t;
    if (i < N_NODES) g_offsets[i + 1] += g_blocksums[blockIdx.x];
    if (i == 0) g_offsets[0] = 0;
}

__global__ void k_place(const int* __restrict__ ei, const float* __restrict__ w) {
    int e = blockIdx.x * blockDim.x + threadIdx.x;
    if (e < N_EDGES) {
        int src = ei[e];
        int dst = ei[N_EDGES + e];
        int pos = g_offsets[dst] + atomicAdd(&g_cursor[dst], 1);
        g_src_sorted[pos]  = src;
        g_norm_sorted[pos] = g_dinv[src] * w[e] * g_dinv[dst];
    }
}

// ----------------------------- GEMM: out[N,DOUT] = X[N,128] @ W[128,DOUT] ----
// Tile: 128 rows x 64 cols, K-tiles of 32. 256 threads, 8x4 micro-tile each.
template <int DOUT>
__global__ void __launch_bounds__(256) k_gemm(const float* __restrict__ X,
                                              const float* __restrict__ W,
                                              float* __restrict__ out) {
    __shared__ float xs[32][132];   // [k][row], padded
    __shared__ float ws[32][64];    // [k][col]

    int tid  = threadIdx.x;
    int row0 = blockIdx.x * 128;
    int col0 = blockIdx.y * 64;
    int tm = tid >> 4;              // 0..15 -> rows tm*8..tm*8+7
    int tn = tid & 15;              // 0..15 -> cols tn*4..tn*4+3

    float acc[8][4];
#pragma unroll
    for (int r = 0; r < 8; r++)
#pragma unroll
        for (int c = 0; c < 4; c++) acc[r][c] = 0.0f;

    for (int kt = 0; kt < 128; kt += 32) {
        // load X tile (128 rows x 32 k) transposed into xs[k][row]
#pragma unroll
        for (int i = 0; i < 4; i++) {
            int s  = tid + i * 256;          // 0..1023
            int r  = s >> 3;                 // 0..127
            int k4 = (s & 7) * 4;            // 0,4,..,28
            int grow = row0 + r;
            float4 v = make_float4(0.f, 0.f, 0.f, 0.f);
            if (grow < N_NODES)
                v = *reinterpret_cast<const float4*>(&X[(size_t)grow * DIM + kt + k4]);
            xs[k4 + 0][r] = v.x;
            xs[k4 + 1][r] = v.y;
            xs[k4 + 2][r] = v.z;
            xs[k4 + 3][r] = v.w;
        }
        // load W tile (32 k x 64 cols)
#pragma unroll
        for (int i = 0; i < 2; i++) {
            int s  = tid + i * 256;          // 0..511
            int k  = s >> 4;                 // 0..31
            int c4 = (s & 15) * 4;           // 0..60
            float4 v = *reinterpret_cast<const float4*>(&W[(size_t)(kt + k) * DOUT + col0 + c4]);
            *reinterpret_cast<float4*>(&ws[k][c4]) = v;
        }
        __syncthreads();

#pragma unroll
        for (int k = 0; k < 32; k++) {
            float4 a0 = *reinterpret_cast<const float4*>(&xs[k][tm * 8]);
            float4 a1 = *reinterpret_cast<const float4*>(&xs[k][tm * 8 + 4]);
            float4 b  = *reinterpret_cast<const float4*>(&ws[k][tn * 4]);
            float av[8] = {a0.x, a0.y, a0.z, a0.w, a1.x, a1.y, a1.z, a1.w};
            float bv[4] = {b.x, b.y, b.z, b.w};
#pragma unroll
            for (int r = 0; r < 8; r++)
#pragma unroll
                for (int c = 0; c < 4; c++) acc[r][c] += av[r] * bv[c];
        }
        __syncthreads();
    }

#pragma unroll
    for (int r = 0; r < 8; r++) {
        int grow = row0 + tm * 8 + r;
        if (grow < N_NODES) {
            float4 v = make_float4(acc[r][0], acc[r][1], acc[r][2], acc[r][3]);
            *reinterpret_cast<float4*>(&out[(size_t)grow * DOUT + col0 + tn * 4]) = v;
        }
    }
}

// ----------------------------- aggregation: warp per node -------------------
// out[i] = bias + self[i]*h[i] + sum_{j in CSR[i]} norm[j] * h[src[j]]
template <int DOUT, bool RELU>
__global__ void __launch_bounds__(256) k_agg(const float* __restrict__ H,
                                             const float* __restrict__ bias,
                                             float* __restrict__ out) {
    int node = (blockIdx.x * blockDim.x + threadIdx.x) >> 5;
    int lane = threadIdx.x & 31;
    if (node >= N_NODES) return;

    constexpr int V = DOUT / 32;   // 4 (128) or 2 (64)

    float acc[V];
    float s = g_self[node];
    if constexpr (V == 4) {
        float4 h = *reinterpret_cast<const float4*>(&H[(size_t)node * DOUT + lane * 4]);
        acc[0] = s * h.x; acc[1] = s * h.y; acc[2] = s * h.z; acc[3] = s * h.w;
    } else {
        float2 h = *reinterpret_cast<const float2*>(&H[(size_t)node * DOUT + lane * 2]);
        acc[0] = s * h.x; acc[1] = s * h.y;
    }

    int beg = g_offsets[node];
    int end = g_offsets[node + 1];
    for (int j = beg; j < end; j++) {
        int   src = g_src_sorted[j];
        float nm  = g_norm_sorted[j];
        if constexpr (V == 4) {
            float4 h = *reinterpret_cast<const float4*>(&H[(size_t)src * DOUT + lane * 4]);
            acc[0] += nm * h.x; acc[1] += nm * h.y; acc[2] += nm * h.z; acc[3] += nm * h.w;
        } else {
            float2 h = *reinterpret_cast<const float2*>(&H[(size_t)src * DOUT + lane * 2]);
            acc[0] += nm * h.x; acc[1] += nm * h.y;
        }
    }

    if constexpr (V == 4) {
        float4 b = *reinterpret_cast<const float4*>(&bias[lane * 4]);
        acc[0] += b.x; acc[1] += b.y; acc[2] += b.z; acc[3] += b.w;
        if (RELU) {
#pragma unroll
            for (int c = 0; c < 4; c++) acc[c] = fmaxf(acc[c], 0.0f);
        }
        *reinterpret_cast<float4*>(&out[(size_t)node * DOUT + lane * 4]) =
            make_float4(acc[0], acc[1], acc[2], acc[3]);
    } else {
        float2 b = *reinterpret_cast<const float2*>(&bias[lane * 2]);
        acc[0] += b.x; acc[1] += b.y;
        if (RELU) {
            acc[0] = fmaxf(acc[0], 0.0f);
            acc[1] = fmaxf(acc[1], 0.0f);
        }
        *reinterpret_cast<float2*>(&out[(size_t)node * DOUT + lane * 2]) =
            make_float2(acc[0], acc[1]);
    }
}

// ----------------------------- launch ---------------------------------------
extern "C" void kernel_launch(void* const* d_in, const int* in_sizes, int n_in,
                              void* d_out, int out_size) {
    const float* x  = (const float*)d_in[0];
    const float* ew = (const float*)d_in[1];
    const int*   ei = (const int*)d_in[2];
    const float* W1 = (const float*)d_in[3];
    const float* b1 = (const float*)d_in[4];
    const float* W2 = (const float*)d_in[5];
    const float* b2 = (const float*)d_in[6];
    const float* W3 = (const float*)d_in[7];
    const float* b3 = (const float*)d_in[8];
    const float* W4 = (const float*)d_in[9];
    const float* b4 = (const float*)d_in[10];
    float* out = (float*)d_out;

    float *bufA, *bufB;
    cudaGetSymbolAddress((void**)&bufA, g_bufA);
    cudaGetSymbolAddress((void**)&bufB, g_bufB);

    const int NB_N  = (N_NODES + 255) / 256;
    const int NB_E  = (N_EDGES + 255) / 256;
    const int NB_SC = (N_NODES + SCAN_BS - 1) / SCAN_BS;

    // ---- preprocessing ----
    k_init_nodes<<<NB_N, 256>>>();
    k_edge_degree<<<NB_E, 256>>>(ei, ew);
    k_dinv<<<NB_N, 256>>>();
    k_scanA<<<NB_SC, SCAN_BS>>>();
    k_scanB<<<1, 32>>>(NB_SC);
    k_scanC<<<NB_SC, SCAN_BS>>>();
    k_place<<<NB_E, 256>>>(ei, ew);

    // ---- layers ----
    dim3 gemm_grid128((N_NODES + 127) / 128, 2);   // DOUT=128 -> 2 col tiles
    dim3 gemm_grid64((N_NODES + 127) / 128, 1);    // DOUT=64
    const int AGG_BLOCKS = (N_NODES * 32 + 255) / 256;   // warp per node

    // layer 1
    k_gemm<128><<<gemm_grid128, 256>>>(x, W1, bufA);
    k_agg<128, true><<<AGG_BLOCKS, 256>>>(bufA, b1, bufB);
    // layer 2
    k_gemm<128><<<gemm_grid128, 256>>>(bufB, W2, bufA);
    k_agg<128, true><<<AGG_BLOCKS, 256>>>(bufA, b2, bufB);
    // layer 3
    k_gemm<128><<<gemm_grid128, 256>>>(bufB, W3, bufA);
    k_agg<128, true><<<AGG_BLOCKS, 256>>>(bufA, b3, bufB);
    // layer 4 (out dim 64, no relu, write directly to d_out)
    k_gemm<64><<<gemm_grid64, 256>>>(bufB, W4, bufA);
    k_agg<64, false><<<AGG_BLOCKS, 256>>>(bufA, b4, out);
}

// round 3
// speedup vs baseline: 1.0007x; 1.0007x over previous
#include <cuda_runtime.h>
#include <cstdint>

// ---------------------------------------------------------------------------
// GCN: 4 layers, N=100000 nodes, E=1600000 edges, 128->128->128->128->64
// Strategy:
//   1. Per-launch preprocessing: deg (with self-loop +1), dinv=rsqrt(deg),
//      CSR-by-destination build (count -> scan -> place).
//   2. Per layer: dense GEMM h = x@W  (fp32 tiled SGEMM, 128x64 tiles)
//                 then warp-per-node aggregation: out[i] = b + sum_j norm_j*h[src_j]
//                 + dinv[i]^2 * h[i] (self loop), fused bias + relu.
// No atomic floats in the hot path; feature matrices (51MB) are L2-resident.
// ---------------------------------------------------------------------------

#define N_NODES 100000
#define N_EDGES 1600000
#define DIM 128

// ----------------------------- scratch (device globals; no allocs allowed) --
__device__ float g_deg[N_NODES];        // degree, then overwritten semantics kept separate
__device__ float g_dinv[N_NODES];
__device__ float g_self[N_NODES];       // dinv^2 (self-loop norm)
__device__ int   g_counts[N_NODES];
__device__ int   g_offsets[N_NODES + 1];
__device__ int   g_cursor[N_NODES];
__device__ int   g_blocksums[256];
__device__ int   g_src_sorted[N_EDGES];
__device__ float g_norm_sorted[N_EDGES];
__device__ float g_bufA[(size_t)N_NODES * DIM];
__device__ float g_bufB[(size_t)N_NODES * DIM];

// ----------------------------- preprocessing kernels ------------------------
__global__ void k_init_nodes() {
    int i = blockIdx.x * blockDim.x + threadIdx.x;
    if (i < N_NODES) {
        g_deg[i]    = 1.0f;   // self-loop weight
        g_counts[i] = 0;
        g_cursor[i] = 0;
    }
}

__global__ void k_edge_degree(const int* __restrict__ ei, const float* __restrict__ w) {
    int e = blockIdx.x * blockDim.x + threadIdx.x;
    if (e < N_EDGES) {
        int dst = ei[N_EDGES + e];
        atomicAdd(&g_deg[dst], w[e]);
        atomicAdd(&g_counts[dst], 1);
    }
}

__global__ void k_dinv() {
    int i = blockIdx.x * blockDim.x + threadIdx.x;
    if (i < N_NODES) {
        float d = g_deg[i];
        float r = (d > 0.0f) ? rsqrtf(d) : 0.0f;
        g_dinv[i] = r;
        g_self[i] = r * r;
    }
}

// ---- exclusive scan of g_counts into g_offsets (3 passes) ----
#define SCAN_BS 1024
__global__ void k_scanA() {
    __shared__ int s[SCAN_BS];
    int t = threadIdx.x;
    int i = blockIdx.x * SCAN_BS + t;
    int v = (i < N_NODES) ? g_counts[i] : 0;
    s[t] = v;
    __syncthreads();
    for (int off = 1; off < SCAN_BS; off <<= 1) {
        int x = (t >= off) ? s[t - off] : 0;
        __syncthreads();
        s[t] += x;
        __syncthreads();
    }
    if (i < N_NODES) g_offsets[i + 1] = s[t];          // inclusive within block
    if (t == SCAN_BS - 1) g_blocksums[blockIdx.x] = s[t];
}

__global__ void k_scanB(int nblocks) {
    if (threadIdx.x == 0 && blockIdx.x == 0) {
        int run = 0;
        for (int b = 0; b < nblocks; b++) {
            int v = g_blocksums[b];
            g_blocksums[b] = run;                      // exclusive
            run += v;
        }
    }
}

__global__ void k_scanC() {
    int t = threadIdx.x;
    int i = blockIdx.x * SCAN_BS + t;
    if (i < N_NODES) g_offsets[i + 1] += g_blocksums[blockIdx.x];
    if (i == 0) g_offsets[0] = 0;
}

__global__ void k_place(const int* __restrict__ ei, const float* __restrict__ w) {
    int e = blockIdx.x * blockDim.x + threadIdx.x;
    if (e < N_EDGES) {
        int src = ei[e];
        int dst = ei[N_EDGES + e];
        int pos = g_offsets[dst] + atomicAdd(&g_cursor[dst], 1);
        g_src_sorted[pos]  = src;
        g_norm_sorted[pos] = g_dinv[src] * w[e] * g_dinv[dst];
    }
}

// ----------------------------- GEMM: out[N,DOUT] = X[N,128] @ W[128,DOUT] ----
// Tile: 128 rows x 64 cols, K-tiles of 32. 256 threads, 8x4 micro-tile each.
template <int DOUT>
__global__ void __launch_bounds__(256) k_gemm(const float* __restrict__ X,
                                              const float* __restrict__ W,
                                              float* __restrict__ out) {
    __shared__ float xs[32][132];   // [k][row], padded
    __shared__ float ws[32][64];    // [k][col]

    int tid  = threadIdx.x;
    int row0 = blockIdx.x * 128;
    int col0 = blockIdx.y * 64;
    int tm = tid >> 4;              // 0..15 -> rows tm*8..tm*8+7
    int tn = tid & 15;              // 0..15 -> cols tn*4..tn*4+3

    float acc[8][4];
#pragma unroll
    for (int r = 0; r < 8; r++)
#pragma unroll
        for (int c = 0; c < 4; c++) acc[r][c] = 0.0f;

    for (int kt = 0; kt < 128; kt += 32) {
        // load X tile (128 rows x 32 k) transposed into xs[k][row]
#pragma unroll
        for (int i = 0; i < 4; i++) {
            int s  = tid + i * 256;          // 0..1023
            int r  = s >> 3;                 // 0..127
            int k4 = (s & 7) * 4;            // 0,4,..,28
            int grow = row0 + r;
            float4 v = make_float4(0.f, 0.f, 0.f, 0.f);
            if (grow < N_NODES)
                v = *reinterpret_cast<const float4*>(&X[(size_t)grow * DIM + kt + k4]);
            xs[k4 + 0][r] = v.x;
            xs[k4 + 1][r] = v.y;
            xs[k4 + 2][r] = v.z;
            xs[k4 + 3][r] = v.w;
        }
        // load W tile (32 k x 64 cols)
#pragma unroll
        for (int i = 0; i < 2; i++) {
            int s  = tid + i * 256;          // 0..511
            int k  = s >> 4;                 // 0..31
            int c4 = (s & 15) * 4;           // 0..60
            float4 v = *reinterpret_cast<const float4*>(&W[(size_t)(kt + k) * DOUT + col0 + c4]);
            *reinterpret_cast<float4*>(&ws[k][c4]) = v;
        }
        __syncthreads();

#pragma unroll
        for (int k = 0; k < 32; k++) {
            float4 a0 = *reinterpret_cast<const float4*>(&xs[k][tm * 8]);
            float4 a1 = *reinterpret_cast<const float4*>(&xs[k][tm * 8 + 4]);
            float4 b  = *reinterpret_cast<const float4*>(&ws[k][tn * 4]);
            float av[8] = {a0.x, a0.y, a0.z, a0.w, a1.x, a1.y, a1.z, a1.w};
            float bv[4] = {b.x, b.y, b.z, b.w};
#pragma unroll
            for (int r = 0; r < 8; r++)
#pragma unroll
                for (int c = 0; c < 4; c++) acc[r][c] += av[r] * bv[c];
        }
        __syncthreads();
    }

#pragma unroll
    for (int r = 0; r < 8; r++) {
        int grow = row0 + tm * 8 + r;
        if (grow < N_NODES) {
            float4 v = make_float4(acc[r][0], acc[r][1], acc[r][2], acc[r][3]);
            *reinterpret_cast<float4*>(&out[(size_t)grow * DOUT + col0 + tn * 4]) = v;
        }
    }
}

// ----------------------------- aggregation: warp per node -------------------
// out[i] = bias + self[i]*h[i] + sum_{j in CSR[i]} norm[j] * h[src[j]]
template <int DOUT, bool RELU>
__global__ void __launch_bounds__(256) k_agg(const float* __restrict__ H,
                                             const float* __restrict__ bias,
                                             float* __restrict__ out) {
    int node = (blockIdx.x * blockDim.x + threadIdx.x) >> 5;
    int lane = threadIdx.x & 31;
    if (node >= N_NODES) return;

    constexpr int V = DOUT / 32;   // 4 (128) or 2 (64)

    float acc[V];
    float s = g_self[node];
    if constexpr (V == 4) {
        float4 h = *reinterpret_cast<const float4*>(&H[(size_t)node * DOUT + lane * 4]);
        acc[0] = s * h.x; acc[1] = s * h.y; acc[2] = s * h.z; acc[3] = s * h.w;
    } else {
        float2 h = *reinterpret_cast<const float2*>(&H[(size_t)node * DOUT + lane * 2]);
        acc[0] = s * h.x; acc[1] = s * h.y;
    }

    int beg = g_offsets[node];
    int end = g_offsets[node + 1];
    for (int j = beg; j < end; j++) {
        int   src = g_src_sorted[j];
        float nm  = g_norm_sorted[j];
        if constexpr (V == 4) {
            float4 h = *reinterpret_cast<const float4*>(&H[(size_t)src * DOUT + lane * 4]);
            acc[0] += nm * h.x; acc[1] += nm * h.y; acc[2] += nm * h.z; acc[3] += nm * h.w;
        } else {
            float2 h = *reinterpret_cast<const float2*>(&H[(size_t)src * DOUT + lane * 2]);
            acc[0] += nm * h.x; acc[1] += nm * h.y;
        }
    }

    if constexpr (V == 4) {
        float4 b = *reinterpret_cast<const float4*>(&bias[lane * 4]);
        acc[0] += b.x; acc[1] += b.y; acc[2] += b.z; acc[3] += b.w;
        if (RELU) {
#pragma unroll
            for (int c = 0; c < 4; c++) acc[c] = fmaxf(acc[c], 0.0f);
        }
        *reinterpret_cast<float4*>(&out[(size_t)node * DOUT + lane * 4]) =
            make_float4(acc[0], acc[1], acc[2], acc[3]);
    } else {
        float2 b = *reinterpret_cast<const float2*>(&bias[lane * 2]);
        acc[0] += b.x; acc[1] += b.y;
        if (RELU) {
            acc[0] = fmaxf(acc[0], 0.0f);
            acc[1] = fmaxf(acc[1], 0.0f);
        }
        *reinterpret_cast<float2*>(&out[(size_t)node * DOUT + lane * 2]) =
            make_float2(acc[0], acc[1]);
    }
}

// ----------------------------- launch ---------------------------------------
extern "C" void kernel_launch(void* const* d_in, const int* in_sizes, int n_in,
                              void* d_out, int out_size) {
    const float* x  = (const float*)d_in[0];
    const float* ew = (const float*)d_in[1];
    const int*   ei = (const int*)d_in[2];
    const float* W1 = (const float*)d_in[3];
    const float* b1 = (const float*)d_in[4];
    const float* W2 = (const float*)d_in[5];
    const float* b2 = (const float*)d_in[6];
    const float* W3 = (const float*)d_in[7];
    const float* b3 = (const float*)d_in[8];
    const float* W4 = (const float*)d_in[9];
    const float* b4 = (const float*)d_in[10];
    float* out = (float*)d_out;

    float *bufA, *bufB;
    cudaGetSymbolAddress((void**)&bufA, g_bufA);
    cudaGetSymbolAddress((void**)&bufB, g_bufB);

    const int NB_N  = (N_NODES + 255) / 256;
    const int NB_E  = (N_EDGES + 255) / 256;
    const int NB_SC = (N_NODES + SCAN_BS - 1) / SCAN_BS;

    // ---- preprocessing ----
    k_init_nodes<<<NB_N, 256>>>();
    k_edge_degree<<<NB_E, 256>>>(ei, ew);
    k_dinv<<<NB_N, 256>>>();
    k_scanA<<<NB_SC, SCAN_BS>>>();
    k_scanB<<<1, 32>>>(NB_SC);
    k_scanC<<<NB_SC, SCAN_BS>>>();
    k_place<<<NB_E, 256>>>(ei, ew);

    // ---- layers ----
    dim3 gemm_grid128((N_NODES + 127) / 128, 2);   // DOUT=128 -> 2 col tiles
    dim3 gemm_grid64((N_NODES + 127) / 128, 1);    // DOUT=64
    const int AGG_BLOCKS = (N_NODES * 32 + 255) / 256;   // warp per node

    // layer 1
    k_gemm<128><<<gemm_grid128, 256>>>(x, W1, bufA);
    k_agg<128, true><<<AGG_BLOCKS, 256>>>(bufA, b1, bufB);
    // layer 2
    k_gemm<128><<<gemm_grid128, 256>>>(bufB, W2, bufA);
    k_agg<128, true><<<AGG_BLOCKS, 256>>>(bufA, b2, bufB);
    // layer 3
    k_gemm<128><<<gemm_grid128, 256>>>(bufB, W3, bufA);
    k_agg<128, true><<<AGG_BLOCKS, 256>>>(bufA, b3, bufB);
    // layer 4 (out dim 64, no relu, write directly to d_out)
    k_gemm<64><<<gemm_grid64, 256>>>(bufB, W4, bufA);
    k_agg<64, false><<<AGG_BLOCKS, 256>>>(bufA, b4, out);
}